// round 11
// baseline (speedup 1.0000x reference)
#include <cuda_runtime.h>
#include <cuda_fp16.h>
#include <cstdint>

// GraphConvLayer via CSR keyed by (dst*5+type), type-contiguous segments,
// fold-at-boundary. This round: fp16 gather payload (fp32 accumulation),
// single-pass decoupled-lookback scan, vectorized hist/scatter, fused inits.

#define NTYPES 5
#define MAXE   1700000
#define MAXN   50001
#define MAXB   (MAXN * NTYPES)
#define SCAN_BS 1024
#define SCAN_ITEMS 4
#define SCAN_TILE (SCAN_BS * SCAN_ITEMS)

__device__ __half g_xh[(size_t)MAXN * 128];
__device__ int g_cnt[MAXB];
__device__ int g_off[MAXB + 1];
__device__ int g_rank[MAXE];
__device__ int g_bin[MAXE];
__device__ int g_packed[MAXE];
__device__ unsigned int g_state[128];

// ---------------- convert x -> fp16, zero g_cnt ----------------

__global__ void convert_kernel(const float* __restrict__ x, int nF4, int B) {
    const int i = blockIdx.x * blockDim.x + threadIdx.x;
    const int stride = gridDim.x * blockDim.x;
    for (int j = i; j < B; j += stride) g_cnt[j] = 0;
    if (i < nF4) {
        float4 v = ((const float4*)x)[i];
        __half2 h0 = __floats2half2_rn(v.x, v.y);
        __half2 h1 = __floats2half2_rn(v.z, v.w);
        uint2 u;
        u.x = *reinterpret_cast<unsigned*>(&h0);
        u.y = *reinterpret_cast<unsigned*>(&h1);
        ((uint2*)g_xh)[i] = u;
    }
}

// ---------------- histogram (x4 vectorized, rank capture) ----------------

__global__ void hist_kernel(const int* __restrict__ dst,
                            const int* __restrict__ et, int E) {
    if (blockIdx.x == 0 && threadIdx.x < 128) g_state[threadIdx.x] = 0;
    const int i = blockIdx.x * blockDim.x + threadIdx.x;
    const int e = i * 4;
    if (e + 3 < E) {
        int4 d = ((const int4*)dst)[i];
        int4 t = ((const int4*)et)[i];
        int b0 = d.x * NTYPES + t.x - 1;
        int b1 = d.y * NTYPES + t.y - 1;
        int b2 = d.z * NTYPES + t.z - 1;
        int b3 = d.w * NTYPES + t.w - 1;
        int r0 = atomicAdd(&g_cnt[b0], 1);
        int r1 = atomicAdd(&g_cnt[b1], 1);
        int r2 = atomicAdd(&g_cnt[b2], 1);
        int r3 = atomicAdd(&g_cnt[b3], 1);
        ((int4*)g_bin)[i]  = make_int4(b0, b1, b2, b3);
        ((int4*)g_rank)[i] = make_int4(r0, r1, r2, r3);
    } else {
        for (int k = e; k < E; k++) {
            int bin = dst[k] * NTYPES + (et[k] - 1);
            g_bin[k]  = bin;
            g_rank[k] = atomicAdd(&g_cnt[bin], 1);
        }
    }
}

// ---------------- single-pass scan (decoupled lookback) ----------------

__device__ __forceinline__ int block_exscan_1024(int v, int* wtot) {
    const int lane = threadIdx.x & 31, w = threadIdx.x >> 5;
    int xv = v;
    #pragma unroll
    for (int s = 1; s < 32; s <<= 1) {
        int y = __shfl_up_sync(0xffffffffu, xv, s);
        if (lane >= s) xv += y;
    }
    if (lane == 31) wtot[w] = xv;
    __syncthreads();
    if (w == 0) {
        int y = wtot[lane];
        #pragma unroll
        for (int s = 1; s < 32; s <<= 1) {
            int z = __shfl_up_sync(0xffffffffu, y, s);
            if (lane >= s) y += z;
        }
        wtot[lane] = y;
    }
    __syncthreads();
    return xv - v + ((w > 0) ? wtot[w - 1] : 0);
}

__global__ void __launch_bounds__(SCAN_BS) scan_lookback(int B, int E) {
    __shared__ int wtot[32];
    __shared__ int s_prev;
    const int bid = blockIdx.x, tid = threadIdx.x;
    const int base = bid * SCAN_TILE + tid * SCAN_ITEMS;

    int4 v = make_int4(0, 0, 0, 0);
    if (base + 3 < B) v = *(const int4*)&g_cnt[base];
    else {
        if (base     < B) v.x = g_cnt[base];
        if (base + 1 < B) v.y = g_cnt[base + 1];
        if (base + 2 < B) v.z = g_cnt[base + 2];
        if (base + 3 < B) v.w = g_cnt[base + 3];
    }
    const int s = v.x + v.y + v.z + v.w;
    const int ex = block_exscan_1024(s, wtot);

    if (tid == SCAN_BS - 1) {
        const int btot = ex + s;
        if (bid == 0) {
            atomicExch(&g_state[0], (2u << 30) | (unsigned)btot);
            s_prev = 0;
        } else {
            atomicExch(&g_state[bid], (1u << 30) | (unsigned)btot);
            int prev = 0;
            for (int j = bid - 1; ; j--) {
                unsigned w;
                do { w = atomicOr(&g_state[j], 0u); } while ((w >> 30) == 0u);
                prev += (int)(w & 0x3FFFFFFFu);
                if ((w >> 30) == 2u) break;
            }
            atomicExch(&g_state[bid], (2u << 30) | (unsigned)(prev + btot));
            s_prev = prev;
        }
    }
    __syncthreads();

    const int off0 = s_prev + ex;
    if (base < B) {
        g_off[base] = off0;
        if (base + 1 < B) g_off[base + 1] = off0 + v.x;
        if (base + 2 < B) g_off[base + 2] = off0 + v.x + v.y;
        if (base + 3 < B) g_off[base + 3] = off0 + v.x + v.y + v.z;
    }
    if (bid == 0 && tid == 0) g_off[B] = E;
}

// ---------------- scatter (x4 vectorized, atomic-free) ----------------

__global__ void scatter_kernel(const int* __restrict__ src, int E) {
    const int i = blockIdx.x * blockDim.x + threadIdx.x;
    const int e = i * 4;
    if (e + 3 < E) {
        int4 sv = ((const int4*)src)[i];
        int4 bv = ((const int4*)g_bin)[i];
        int4 rv = ((const int4*)g_rank)[i];
        g_packed[g_off[bv.x] + rv.x] = sv.x;
        g_packed[g_off[bv.y] + rv.y] = sv.y;
        g_packed[g_off[bv.z] + rv.z] = sv.z;
        g_packed[g_off[bv.w] + rv.w] = sv.w;
    } else {
        for (int k = e; k < E; k++)
            g_packed[g_off[g_bin[k]] + g_rank[k]] = src[k];
    }
}

// ---------------- main: warp per node, fp16 gather, fp32 accumulate ----------------

__global__ void __launch_bounds__(256)
gcl_main(const float* __restrict__ W,
         const float* __restrict__ Bv,
         float* __restrict__ out, int N)
{
    __shared__ float Wsh[NTYPES][8][8];
    __shared__ float Bsh[NTYPES][8];
    __shared__ float aggS[8][8][16];

    const int tid = threadIdx.x;
    for (int i = tid; i < NTYPES * 64; i += 256) {
        int t = i >> 6, rem = i & 63;
        Wsh[t][rem >> 3][rem & 7] = W[i];
    }
    for (int i = tid; i < NTYPES * 8; i += 256) Bsh[i >> 3][i & 7] = Bv[i];
    __syncthreads();

    const int lane = tid & 31, wl = tid >> 5;
    const int n = blockIdx.x * 8 + wl;
    if (n >= N) return;

    const int myBnd = g_off[n * NTYPES + ((lane < NTYPES + 1) ? lane : NTYPES)];
    const int beg = __shfl_sync(0xffffffffu, myBnd, 0);
    const int end = __shfl_sync(0xffffffffu, myBnd, NTYPES);

    const int o  = lane >> 2;
    const int cg = lane & 3;

    float a0 = 0.f, a1 = 0.f, a2 = 0.f, a3 = 0.f;       // running per-type sum
    float ax = 0.f, ay = 0.f, az = 0.f, aw = 0.f;       // transformed output

    int tcur = 0;
    int nextB = __shfl_sync(0xffffffffu, myBnd, 1);

    const uint2* __restrict__ xh = (const uint2*)g_xh;  // 4 halves per uint2

    for (int base = beg; base < end; base += 32) {
        const int j32 = base + lane;
        const int pk = (j32 < end) ? g_packed[j32] : 0;
        int m = end - base; if (m > 32) m = 32;

        uint2 v0, v1, v2, v3;
        {
            int s0 = __shfl_sync(0xffffffffu, pk, 0);
            int s1 = __shfl_sync(0xffffffffu, pk, (1 < m) ? 1 : 0);
            int s2 = __shfl_sync(0xffffffffu, pk, (2 < m) ? 2 : 0);
            int s3 = __shfl_sync(0xffffffffu, pk, (3 < m) ? 3 : 0);
            v0 = xh[(size_t)s0 * 32 + lane];
            v1 = xh[(size_t)s1 * 32 + lane];
            v2 = xh[(size_t)s2 * 32 + lane];
            v3 = xh[(size_t)s3 * 32 + lane];
        }

        for (int k0 = 0; k0 < m; k0 += 4) {
            uint2 c0 = v0, c1 = v1, c2 = v2, c3 = v3;
            if (k0 + 4 < m) {
                int k4 = k0 + 4;
                int s0 = __shfl_sync(0xffffffffu, pk, k4);
                int s1 = __shfl_sync(0xffffffffu, pk, (k4 + 1 < m) ? k4 + 1 : k4);
                int s2 = __shfl_sync(0xffffffffu, pk, (k4 + 2 < m) ? k4 + 2 : k4);
                int s3 = __shfl_sync(0xffffffffu, pk, (k4 + 3 < m) ? k4 + 3 : k4);
                v0 = xh[(size_t)s0 * 32 + lane];
                v1 = xh[(size_t)s1 * 32 + lane];
                v2 = xh[(size_t)s2 * 32 + lane];
                v3 = xh[(size_t)s3 * 32 + lane];
            }

            #pragma unroll
            for (int q = 0; q < 4; q++) {
                const int k = k0 + q;
                if (k < m) {
                    const int j = base + k;
                    while (j >= nextB) {   // warp-uniform type-boundary fold
                        *(float4*)(&aggS[wl][o][cg * 4]) =
                            make_float4(a0, a1, a2, a3);
                        __syncwarp();
                        #pragma unroll
                        for (int i = 0; i < 8; i++) {
                            const float wv = Wsh[tcur][o][i];
                            const float4 a = *(const float4*)(&aggS[wl][i][cg * 4]);
                            ax += wv * a.x; ay += wv * a.y;
                            az += wv * a.z; aw += wv * a.w;
                        }
                        __syncwarp();
                        a0 = a1 = a2 = a3 = 0.f;
                        tcur++;
                        nextB = __shfl_sync(0xffffffffu, myBnd,
                                            (tcur < NTYPES) ? (tcur + 1) : NTYPES);
                    }
                    const uint2 vc = (q == 0) ? c0 : (q == 1) ? c1
                                   : (q == 2) ? c2 : c3;
                    __half2 h0 = *reinterpret_cast<const __half2*>(&vc.x);
                    __half2 h1 = *reinterpret_cast<const __half2*>(&vc.y);
                    float2 f0 = __half22float2(h0);
                    float2 f1 = __half22float2(h1);
                    a0 += f0.x; a1 += f0.y; a2 += f1.x; a3 += f1.y;
                }
            }
        }
    }

    // final fold
    *(float4*)(&aggS[wl][o][cg * 4]) = make_float4(a0, a1, a2, a3);
    __syncwarp();
    #pragma unroll
    for (int i = 0; i < 8; i++) {
        const float wv = Wsh[tcur][o][i];
        const float4 a = *(const float4*)(&aggS[wl][i][cg * 4]);
        ax += wv * a.x; ay += wv * a.y; az += wv * a.z; aw += wv * a.w;
    }

    float bias = 0.f;
    #pragma unroll
    for (int t = 0; t < NTYPES; t++) {
        int lo = __shfl_sync(0xffffffffu, myBnd, t);
        int hi = __shfl_sync(0xffffffffu, myBnd, t + 1);
        bias += (float)(hi - lo) * Bsh[t][o];
    }

    float4 res = { ax + bias, ay + bias, az + bias, aw + bias };
    *(float4*)(out + (size_t)n * 128 + o * 16 + cg * 4) = res;
}

// ---------------- launch ----------------

extern "C" void kernel_launch(void* const* d_in, const int* in_sizes, int n_in,
                              void* d_out, int out_size)
{
    const float* x   = (const float*)d_in[0];
    const float* W   = (const float*)d_in[1];
    const float* Bv  = (const float*)d_in[2];
    const int*   src = (const int*)  d_in[3];
    const int*   dst = (const int*)  d_in[4];
    const int*   et  = (const int*)  d_in[5];
    float*       out = (float*)d_out;

    const int E = in_sizes[3];
    const int N = in_sizes[0] / 128;
    const int B = N * NTYPES;
    const int nF4 = N * 32;          // x float4 count

    const int tb = 256;
    int cgrid = ((nF4 > B ? nF4 : B) + tb - 1) / tb;
    convert_kernel<<<cgrid, tb>>>(x, nF4, B);

    const int e4 = (E + 3) / 4;
    hist_kernel<<<(e4 + tb - 1) / tb, tb>>>(dst, et, E);

    scan_lookback<<<(B + SCAN_TILE - 1) / SCAN_TILE, SCAN_BS>>>(B, E);

    scatter_kernel<<<(e4 + tb - 1) / tb, tb>>>(src, E);

    gcl_main<<<(N + 7) / 8, 256>>>(W, Bv, out, N);
}